// round 8
// baseline (speedup 1.0000x reference)
#include <cuda_runtime.h>
#include <math.h>
#include <stdint.h>

#define D_EMBED 1024
#define S_LEN   2048
#define BATCH   2
#define NHEADS  16
#define DH      64

__device__ float g_qkv [(size_t)BATCH * S_LEN * 3 * D_EMBED];  // [B,S,3D]
__device__ float g_attn[(size_t)BATCH * S_LEN * D_EMBED];      // [B,S,D]

// ===========================================================================
// Helpers
// ===========================================================================
__device__ __forceinline__ uint32_t smem_u32(const void* p) {
    uint32_t a;
    asm("{ .reg .u64 t; cvta.to.shared.u64 t, %1; cvt.u32.u64 %0, t; }"
        : "=r"(a) : "l"(p));
    return a;
}

// bf16 m16n8k16 mma: D += A(16x16 row) * B(16x8 col), fp32 accum
__device__ __forceinline__ void mma_bf16(float* d, const uint32_t* a, const uint32_t* b) {
    asm volatile(
        "mma.sync.aligned.m16n8k16.row.col.f32.bf16.bf16.f32 "
        "{%0,%1,%2,%3}, {%4,%5,%6,%7}, {%8,%9}, {%0,%1,%2,%3};\n"
        : "+f"(d[0]), "+f"(d[1]), "+f"(d[2]), "+f"(d[3])
        : "r"(a[0]), "r"(a[1]), "r"(a[2]), "r"(a[3]), "r"(b[0]), "r"(b[1]));
}

// ldmatrix x4: four 8x8 b16 matrices, addresses from lanes 0-7/8-15/16-23/24-31
__device__ __forceinline__ void ldmx4(uint32_t* r, uint32_t addr) {
    asm volatile(
        "ldmatrix.sync.aligned.m8n8.x4.shared.b16 {%0,%1,%2,%3}, [%4];"
        : "=r"(r[0]), "=r"(r[1]), "=r"(r[2]), "=r"(r[3]) : "r"(addr));
}

// bf16x3 split-and-pack: (f0,f1) -> hi = {bf16(f1)|bf16(f0)}, lo = residuals.
__device__ __forceinline__ void bf16x3_pack(float f0, float f1,
                                            uint32_t& hi, uint32_t& lo) {
    asm("cvt.rn.bf16x2.f32 %0, %1, %2;" : "=r"(hi) : "f"(f1), "f"(f0));
    float r0 = f0 - __uint_as_float(hi << 16);
    float r1 = f1 - __uint_as_float(hi & 0xFFFF0000u);
    asm("cvt.rn.bf16x2.f32 %0, %1, %2;" : "=r"(lo) : "f"(r1), "f"(r0));
}

// ===========================================================================
// bf16x3 tensor-core GEMM: C[M,N] = A[M,K] @ B[K,N] + bias
// 128x128 CTA tile, BK=32, 512 threads (16 warps, 4m x 4n), warp tile 32x32.
// Double-buffered smem planes; ldmatrix.x4 fragment loads; loop order
// LDG(t+1) -> MMA(buf t) -> split/STS(buf t+1) -> sync  (STS hides behind
// the tensor-pipe drain).
// Plane layout per stage (u32 offsets): AHI 0, ALO 2560, BHI 5120, BLO 7680;
// rows stride 20 u32 (80 B). Stage size 10240 u32 = 40960 B, 2 stages.
// ===========================================================================
#define G_STAGE_U32 10240
#define G_SMEM_BYTES (2 * G_STAGE_U32 * 4)   // 81920

__global__ __launch_bounds__(512) void gemm_bf16x3(
    const float* __restrict__ A, const float* __restrict__ B,
    const float* __restrict__ bias, float* __restrict__ C,
    int M, int N, int K)
{
    extern __shared__ uint32_t s32[];
    const uint32_t sbase = smem_u32(s32);

    const int tid  = threadIdx.x;
    const int lane = tid & 31;
    const int wid  = tid >> 5;
    const int g    = lane >> 2;
    const int tg   = lane & 3;
    const int wm   = wid & 3;
    const int wn   = wid >> 2;
    const int rowA0 = blockIdx.y * 128;
    const int colB0 = blockIdx.x * 128;

    // loader coordinates
    const int ar0 = tid >> 3;       // A row (and ar0+64)
    const int aj  = tid & 7;        // float4 index along k
    const int bn  = tid & 127;      // B column (n)
    const int bk0 = tid >> 7;       // k-pair base; pairs bk0+4i

    // ldmatrix lane base addresses (stage 0; add stage/ks offsets later)
    const uint32_t a_lane = (uint32_t)((wm * 32 + (lane & 15)) * 80 + ((lane >> 4) << 4));
    const uint32_t b_lane = (uint32_t)((wn * 32 + (lane & 15)) * 80 + ((lane >> 4) << 4));
    const uint32_t AHIa = sbase + a_lane;                 // + mt*1280 + ks*32
    const uint32_t ALOa = sbase + 2560 * 4 + a_lane;
    const uint32_t BHIa = sbase + 5120 * 4 + b_lane;      // + pair*1280 + ks*32
    const uint32_t BLOa = sbase + 7680 * 4 + b_lane;

    float acc[2][4][4];
#pragma unroll
    for (int mt = 0; mt < 2; mt++)
#pragma unroll
        for (int nt = 0; nt < 4; nt++)
#pragma unroll
            for (int i = 0; i < 4; i++) acc[mt][nt][i] = 0.f;

    const int T = K / 32;

    float4 av[2];
    float  bv0[4], bv1[4];

    // ---- prefetch tile 0 + split-store into stage 0 ----
#pragma unroll
    for (int i = 0; i < 2; i++)
        av[i] = *reinterpret_cast<const float4*>(
            A + (size_t)(rowA0 + ar0 + i * 64) * K + aj * 4);
#pragma unroll
    for (int i = 0; i < 4; i++) {
        const float* bp = B + (size_t)(2 * (bk0 + 4 * i)) * N + colB0 + bn;
        bv0[i] = bp[0];
        bv1[i] = bp[N];
    }
    {
        uint32_t* AHI = s32;
        uint32_t* ALO = s32 + 2560;
        uint32_t* BHI = s32 + 5120;
        uint32_t* BLO = s32 + 7680;
#pragma unroll
        for (int i = 0; i < 2; i++) {
            uint32_t h0, l0, h1, l1;
            bf16x3_pack(av[i].x, av[i].y, h0, l0);
            bf16x3_pack(av[i].z, av[i].w, h1, l1);
            const int o = (ar0 + i * 64) * 20 + aj * 2;
            AHI[o] = h0; AHI[o + 1] = h1;
            ALO[o] = l0; ALO[o + 1] = l1;
        }
#pragma unroll
        for (int i = 0; i < 4; i++) {
            uint32_t hh, ll;
            bf16x3_pack(bv0[i], bv1[i], hh, ll);
            const int o = bn * 20 + bk0 + 4 * i;
            BHI[o] = hh; BLO[o] = ll;
        }
    }
    __syncthreads();

    for (int t = 0; t < T; t++) {
        const uint32_t stg = (uint32_t)(t & 1) * (G_STAGE_U32 * 4);
        const bool more = (t + 1 < T);

        // ---- LDG tile t+1 ----
        if (more) {
            const int k0n = (t + 1) * 32;
#pragma unroll
            for (int i = 0; i < 2; i++)
                av[i] = *reinterpret_cast<const float4*>(
                    A + (size_t)(rowA0 + ar0 + i * 64) * K + k0n + aj * 4);
#pragma unroll
            for (int i = 0; i < 4; i++) {
                const float* bp = B + (size_t)(k0n + 2 * (bk0 + 4 * i)) * N + colB0 + bn;
                bv0[i] = bp[0];
                bv1[i] = bp[N];
            }
        }

        // ---- MMA on stage t&1 ----
#pragma unroll
        for (int ks = 0; ks < 2; ks++) {
            const uint32_t ko = stg + ks * 32;
            uint32_t aH[2][4], aL[2][4], bH[4][2], bL[4][2], q[4];
            ldmx4(aL[0], ALOa + ko);
            ldmx4(aL[1], ALOa + ko + 1280);
            ldmx4(aH[0], AHIa + ko);
            ldmx4(aH[1], AHIa + ko + 1280);
            ldmx4(q, BHIa + ko);
            bH[0][0] = q[0]; bH[1][0] = q[1]; bH[0][1] = q[2]; bH[1][1] = q[3];
            ldmx4(q, BHIa + ko + 1280);
            bH[2][0] = q[0]; bH[3][0] = q[1]; bH[2][1] = q[2]; bH[3][1] = q[3];
            ldmx4(q, BLOa + ko);
            bL[0][0] = q[0]; bL[1][0] = q[1]; bL[0][1] = q[2]; bL[1][1] = q[3];
            ldmx4(q, BLOa + ko + 1280);
            bL[2][0] = q[0]; bL[3][0] = q[1]; bL[2][1] = q[2]; bL[3][1] = q[3];

#pragma unroll
            for (int mt = 0; mt < 2; mt++)
#pragma unroll
                for (int nt = 0; nt < 4; nt++)
                    mma_bf16(acc[mt][nt], aL[mt], bH[nt]);
#pragma unroll
            for (int mt = 0; mt < 2; mt++)
#pragma unroll
                for (int nt = 0; nt < 4; nt++)
                    mma_bf16(acc[mt][nt], aH[mt], bH[nt]);
#pragma unroll
            for (int mt = 0; mt < 2; mt++)
#pragma unroll
                for (int nt = 0; nt < 4; nt++)
                    mma_bf16(acc[mt][nt], aH[mt], bL[nt]);
        }

        // ---- split/STS tile t+1 into the other stage ----
        if (more) {
            uint32_t* stp = s32 + ((t + 1) & 1) * G_STAGE_U32;
            uint32_t* AHI = stp;
            uint32_t* ALO = stp + 2560;
            uint32_t* BHI = stp + 5120;
            uint32_t* BLO = stp + 7680;
#pragma unroll
            for (int i = 0; i < 2; i++) {
                uint32_t h0, l0, h1, l1;
                bf16x3_pack(av[i].x, av[i].y, h0, l0);
                bf16x3_pack(av[i].z, av[i].w, h1, l1);
                const int o = (ar0 + i * 64) * 20 + aj * 2;
                AHI[o] = h0; AHI[o + 1] = h1;
                ALO[o] = l0; ALO[o + 1] = l1;
            }
#pragma unroll
            for (int i = 0; i < 4; i++) {
                uint32_t hh, ll;
                bf16x3_pack(bv0[i], bv1[i], hh, ll);
                const int o = bn * 20 + bk0 + 4 * i;
                BHI[o] = hh; BLO[o] = ll;
            }
        }
        __syncthreads();
    }

    // ---- epilogue: bias + store ----
#pragma unroll
    for (int mt = 0; mt < 2; mt++) {
        const int row = rowA0 + wm * 32 + mt * 16 + g;
#pragma unroll
        for (int nt = 0; nt < 4; nt++) {
            const int col = colB0 + wn * 32 + nt * 8 + 2 * tg;
            const float b0v = bias[col], b1v = bias[col + 1];
            *reinterpret_cast<float2*>(&C[(size_t)row * N + col]) =
                make_float2(acc[mt][nt][0] + b0v, acc[mt][nt][1] + b1v);
            *reinterpret_cast<float2*>(&C[(size_t)(row + 8) * N + col]) =
                make_float2(acc[mt][nt][2] + b0v, acc[mt][nt][3] + b1v);
        }
    }
}

// ===========================================================================
// Flash attention, bf16x3 mma.sync (unchanged from Round 7 — passing).
// ===========================================================================
#define AT_SMEM_BYTES 56320

__global__ __launch_bounds__(128) void flash_attn_bf16x3(
    const float* __restrict__ qkv, float* __restrict__ out)
{
    extern __shared__ uint32_t s32[];
    uint32_t* QHI  = s32;            // 4608 u32
    uint32_t* QLO  = s32 + 4608;
    uint32_t* KHI  = s32 + 9216;     // 1152 u32
    uint32_t* KLO  = s32 + 10368;
    uint32_t* VTHI = s32 + 11520;    // 1280 u32
    uint32_t* VTLO = s32 + 12800;

    const int t    = threadIdx.x;
    const int lane = t & 31;
    const int w    = t >> 5;
    const int g    = lane >> 2;
    const int tg   = lane & 3;
    const int bh   = blockIdx.y;
    const int b    = bh >> 4;
    const int h    = bh & 15;
    const int q0   = blockIdx.x * 128;
    const size_t brow = (size_t)b * S_LEN;
    const int rs   = 3 * D_EMBED;
    const int qb   = w * 32;

    // ---- load + split Q tile [128 x 64] (once) ----
#pragma unroll
    for (int i = 0; i < 16; i++) {
        int f  = t + i * 128;
        int r  = f >> 4;
        int c4 = f & 15;
        float4 v = *reinterpret_cast<const float4*>(
            qkv + (brow + q0 + r) * rs + h * DH + c4 * 4);
        uint32_t h0, l0, h1, l1;
        bf16x3_pack(v.x, v.y, h0, l0);
        bf16x3_pack(v.z, v.w, h1, l1);
        const int o = r * 36 + c4 * 2;
        QHI[o] = h0; QHI[o + 1] = h1;
        QLO[o] = l0; QLO[o + 1] = l1;
    }

    float oacc[2][8][4];
#pragma unroll
    for (int mt = 0; mt < 2; mt++)
#pragma unroll
        for (int nt = 0; nt < 8; nt++)
#pragma unroll
            for (int i = 0; i < 4; i++) oacc[mt][nt][i] = 0.f;
    float lrow[2][2] = {{0.f, 0.f}, {0.f, 0.f}};

    for (int kt = 0; kt < S_LEN / 32; kt++) {
        __syncthreads();   // prior tile's K/V frag loads complete
        // ---- load + split K tile [32 keys x 64 d] ----
#pragma unroll
        for (int i = 0; i < 4; i++) {
            int f  = t + i * 128;
            int r  = f >> 4;
            int c4 = f & 15;
            float4 v = *reinterpret_cast<const float4*>(
                qkv + (brow + kt * 32 + r) * rs + D_EMBED + h * DH + c4 * 4);
            uint32_t h0, l0, h1, l1;
            bf16x3_pack(v.x, v.y, h0, l0);
            bf16x3_pack(v.z, v.w, h1, l1);
            const int o = r * 36 + c4 * 2;
            KHI[o] = h0; KHI[o + 1] = h1;
            KLO[o] = l0; KLO[o + 1] = l1;
        }
        // ---- load + split + transpose V tile -> VT[dv][key] ----
#pragma unroll
        for (int i = 0; i < 8; i++) {
            int f  = t + i * 128;
            int kp = f >> 6;    // key pair 0..15
            int dv = f & 63;
            const float* vp = qkv + (brow + kt * 32 + 2 * kp) * rs
                              + 2 * D_EMBED + h * DH + dv;
            float f0 = vp[0], f1 = vp[rs];
            uint32_t hh, ll;
            bf16x3_pack(f0, f1, hh, ll);
            const int o = dv * 20 + kp;
            VTHI[o] = hh; VTLO[o] = ll;
        }
        __syncthreads();

        // ---- S = Q K^T : [32q x 32k] per warp, 4 ksteps of 16, bf16x3 ----
        float sacc[2][4][4];
#pragma unroll
        for (int mt = 0; mt < 2; mt++)
#pragma unroll
            for (int nt = 0; nt < 4; nt++)
#pragma unroll
                for (int i = 0; i < 4; i++) sacc[mt][nt][i] = 0.f;

#pragma unroll
        for (int ks = 0; ks < 4; ks++) {
            uint32_t afr[2][4], bfr[4][2];
            // pass 1: Q_lo * K_hi
#pragma unroll
            for (int nt = 0; nt < 4; nt++) {
                const int ki = (nt * 8 + g) * 36 + ks * 8 + tg;
                bfr[nt][0] = KHI[ki]; bfr[nt][1] = KHI[ki + 4];
            }
#pragma unroll
            for (int mt = 0; mt < 2; mt++) {
                const int qi = (qb + mt * 16 + g) * 36 + ks * 8 + tg;
                afr[mt][0] = QLO[qi];     afr[mt][1] = QLO[qi + 288];
                afr[mt][2] = QLO[qi + 4]; afr[mt][3] = QLO[qi + 292];
            }
#pragma unroll
            for (int mt = 0; mt < 2; mt++)
#pragma unroll
                for (int nt = 0; nt < 4; nt++)
                    mma_bf16(sacc[mt][nt], afr[mt], bfr[nt]);
            // pass 2: Q_hi * K_hi
#pragma unroll
            for (int mt = 0; mt < 2; mt++) {
                const int qi = (qb + mt * 16 + g) * 36 + ks * 8 + tg;
                afr[mt][0] = QHI[qi];     afr[mt][1] = QHI[qi + 288];
                afr[mt][2] = QHI[qi + 4]; afr[mt][3] = QHI[qi + 292];
            }
#pragma unroll
            for (int mt = 0; mt < 2; mt++)
#pragma unroll
                for (int nt = 0; nt < 4; nt++)
                    mma_bf16(sacc[mt][nt], afr[mt], bfr[nt]);
            // pass 3: Q_hi * K_lo
#pragma unroll
            for (int nt = 0; nt < 4; nt++) {
                const int ki = (nt * 8 + g) * 36 + ks * 8 + tg;
                bfr[nt][0] = KLO[ki]; bfr[nt][1] = KLO[ki + 4];
            }
#pragma unroll
            for (int mt = 0; mt < 2; mt++)
#pragma unroll
                for (int nt = 0; nt < 4; nt++)
                    mma_bf16(sacc[mt][nt], afr[mt], bfr[nt]);
        }

        // ---- P = exp(S/8): accumulate l, pack C-frags -> A-frags ----
        uint32_t phi[2][4][2], plo[2][4][2];
#pragma unroll
        for (int mt = 0; mt < 2; mt++)
#pragma unroll
            for (int nt = 0; nt < 4; nt++) {
                float p0 = __expf(0.125f * sacc[mt][nt][0]);
                float p1 = __expf(0.125f * sacc[mt][nt][1]);
                float p2 = __expf(0.125f * sacc[mt][nt][2]);
                float p3 = __expf(0.125f * sacc[mt][nt][3]);
                lrow[mt][0] += p0 + p1;
                lrow[mt][1] += p2 + p3;
                bf16x3_pack(p0, p1, phi[mt][nt][0], plo[mt][nt][0]);
                bf16x3_pack(p2, p3, phi[mt][nt][1], plo[mt][nt][1]);
            }

        // ---- O += P V : 2 ksteps of 16 keys, bf16x3, A from registers ----
#pragma unroll
        for (int s = 0; s < 2; s++) {
            uint32_t vfr[8][2], ah[2][4], al[2][4];
#pragma unroll
            for (int mt = 0; mt < 2; mt++) {
                ah[mt][0] = phi[mt][2 * s][0];     ah[mt][1] = phi[mt][2 * s][1];
                ah[mt][2] = phi[mt][2 * s + 1][0]; ah[mt][3] = phi[mt][2 * s + 1][1];
                al[mt][0] = plo[mt][2 * s][0];     al[mt][1] = plo[mt][2 * s][1];
                al[mt][2] = plo[mt][2 * s + 1][0]; al[mt][3] = plo[mt][2 * s + 1][1];
            }
            // pass 1: P_lo * V_hi
#pragma unroll
            for (int nt = 0; nt < 8; nt++) {
                const int vi = (nt * 8 + g) * 20 + s * 8 + tg;
                vfr[nt][0] = VTHI[vi]; vfr[nt][1] = VTHI[vi + 4];
            }
#pragma unroll
            for (int mt = 0; mt < 2; mt++)
#pragma unroll
                for (int nt = 0; nt < 8; nt++)
                    mma_bf16(oacc[mt][nt], al[mt], vfr[nt]);
            // pass 2: P_hi * V_hi
#pragma unroll
            for (int mt = 0; mt < 2; mt++)
#pragma unroll
                for (int nt = 0; nt < 8; nt++)
                    mma_bf16(oacc[mt][nt], ah[mt], vfr[nt]);
            // pass 3: P_hi * V_lo
#pragma unroll
            for (int nt = 0; nt < 8; nt++) {
                const int vi = (nt * 8 + g) * 20 + s * 8 + tg;
                vfr[nt][0] = VTLO[vi]; vfr[nt][1] = VTLO[vi + 4];
            }
#pragma unroll
            for (int mt = 0; mt < 2; mt++)
#pragma unroll
                for (int nt = 0; nt < 8; nt++)
                    mma_bf16(oacc[mt][nt], ah[mt], vfr[nt]);
        }
    }

    // ---- finalize l (4 threads share each row) ----
#pragma unroll
    for (int mt = 0; mt < 2; mt++)
#pragma unroll
        for (int hf = 0; hf < 2; hf++) {
            float v = lrow[mt][hf];
            v += __shfl_xor_sync(0xffffffff, v, 1);
            v += __shfl_xor_sync(0xffffffff, v, 2);
            lrow[mt][hf] = 1.0f / v;
        }

    // ---- write O = acc / l ----
#pragma unroll
    for (int mt = 0; mt < 2; mt++) {
        int r0 = q0 + qb + mt * 16 + g;
        float* o0 = out + (brow + r0) * D_EMBED + h * DH;
        float* o1 = o0 + 8 * D_EMBED;
#pragma unroll
        for (int nt = 0; nt < 8; nt++) {
            *reinterpret_cast<float2*>(o0 + nt * 8 + 2 * tg) =
                make_float2(oacc[mt][nt][0] * lrow[mt][0],
                            oacc[mt][nt][1] * lrow[mt][0]);
            *reinterpret_cast<float2*>(o1 + nt * 8 + 2 * tg) =
                make_float2(oacc[mt][nt][2] * lrow[mt][1],
                            oacc[mt][nt][3] * lrow[mt][1]);
        }
    }
}

// ===========================================================================
extern "C" void kernel_launch(void* const* d_in, const int* in_sizes, int n_in,
                              void* d_out, int out_size)
{
    const float* x     = (const float*)d_in[0];
    const float* W_in  = (const float*)d_in[1];
    const float* b_in  = (const float*)d_in[2];
    const float* W_out = (const float*)d_in[3];
    const float* b_out = (const float*)d_in[4];
    float* out = (float*)d_out;

    float* qkv  = nullptr;
    float* attn = nullptr;
    cudaGetSymbolAddress((void**)&qkv,  g_qkv);
    cudaGetSymbolAddress((void**)&attn, g_attn);

    const int M = BATCH * S_LEN;
    const int D = D_EMBED;

    cudaFuncSetAttribute(gemm_bf16x3,
                         cudaFuncAttributeMaxDynamicSharedMemorySize, G_SMEM_BYTES);
    cudaFuncSetAttribute(flash_attn_bf16x3,
                         cudaFuncAttributeMaxDynamicSharedMemorySize, AT_SMEM_BYTES);

    // 1) QKV projection (bf16x3 TC, ldmatrix + double buffer)
    {
        dim3 grid(3 * D / 128, M / 128);
        gemm_bf16x3<<<grid, 512, G_SMEM_BYTES>>>(x, W_in, b_in, qkv, M, 3 * D, D);
    }
    // 2) bf16x3 attention
    {
        dim3 grid(S_LEN / 128, BATCH * NHEADS);
        flash_attn_bf16x3<<<grid, 128, AT_SMEM_BYTES>>>(qkv, attn);
    }
    // 3) Output projection (bf16x3 TC)
    {
        dim3 grid(D / 128, M / 128);
        gemm_bf16x3<<<grid, 512, G_SMEM_BYTES>>>(attn, W_out, b_out, out, M, D, D);
    }
}